// round 8
// baseline (speedup 1.0000x reference)
#include <cuda_runtime.h>
#include <math.h>

constexpr int NDIM  = 80;
constexpr int BATCH = 64;
constexpr int SEQ   = 1000;
constexpr int KST   = 12;
constexpr int NBK   = BATCH * KST;   // 768
constexpr int ST    = 128;           // samples per block (kernel B)
constexpr int KPB   = 3;             // k's per block
constexpr int KGRP  = KST / KPB;     // 4
constexpr int MST   = 84;            // msh row stride
constexpr int DST   = 132;           // ds row stride
constexpr int AST   = 82;            // chol row stride (ull lane-stride 41 mod 16 = 9 -> conflict-free)

constexpr float LOG_2PI = 1.837877066409345339082f;
constexpr float EPS = 1e-5f;

__device__ float g_minvT[(size_t)NBK * NDIM * NDIM];
__device__ float g_logdet[NBK];
__device__ float g_negc[(size_t)NBK * NDIM];   // -Lc^-1*mu per (b,k)

typedef unsigned long long ull;
__device__ __forceinline__ ull fma2(ull a, ull b, ull c) {
    ull d; asm("fma.rn.f32x2 %0,%1,%2,%3;" : "=l"(d) : "l"(a), "l"(b), "l"(c)); return d;
}
__device__ __forceinline__ ull mul2(ull a, ull b) {
    ull d; asm("mul.rn.f32x2 %0,%1,%2;" : "=l"(d) : "l"(a), "l"(b)); return d;
}
__device__ __forceinline__ ull add2(ull a, ull b) {
    ull d; asm("add.rn.f32x2 %0,%1,%2;" : "=l"(d) : "l"(a), "l"(b)); return d;
}
__device__ __forceinline__ ull dup2(float x) {
    ull d; asm("mov.b64 %0,{%1,%1};" : "=l"(d) : "f"(x)); return d;
}
__device__ __forceinline__ float2 asf2(ull v) {
    float2 r; asm("mov.b64 {%0,%1},%2;" : "=f"(r.x), "=f"(r.y) : "l"(v)); return r;
}

// ---------------------------------------------------------------------------
// Kernel A: per (b,k). Fused Gauss-Jordan on [Sigma | I]:
// elimination rank-1 updates applied to both A (lower tri) and E (= L_unit^-1
// built incrementally). Lc^-1 = diag(rinv) * E. 160 threads: tid<80 owns the
// E-segment of row tid; tid>=80 owns the A-segment of row tid-80.
// ---------------------------------------------------------------------------
__global__ __launch_bounds__(160) void chol_inv_kernel(const float* __restrict__ sigma,
                                                       const float* __restrict__ mu) {
    __shared__ __align__(16) float A[NDIM * AST];      // 26.2 KB
    __shared__ __align__(16) float E[NDIM * AST];      // 26.2 KB
    __shared__ __align__(16) float colbuf[NDIM + 2];
    __shared__ float rinv[NDIM];
    __shared__ float lbuf[NDIM];
    __shared__ float mush[NDIM];
    __shared__ float dinvsh;

    const int bk  = blockIdx.x;
    const int tid = threadIdx.x;
    const int row = (tid < NDIM) ? tid : tid - NDIM;
    const bool isE = (tid < NDIM);
    const float* Sg = sigma + (size_t)bk * NDIM * NDIM;

    for (int idx = tid; idx < NDIM * NDIM; idx += 160) {
        int r = idx / NDIM, c = idx % NDIM;
        float v = Sg[idx];
        if (r == c) v += EPS;
        A[r * AST + c] = v;
    }
    for (int idx = tid; idx < NDIM * AST; idx += 160) E[idx] = 0.0f;
    if (tid < NDIM) mush[tid] = mu[(size_t)bk * NDIM + tid];
    __syncthreads();
    if (tid < NDIM) E[tid * AST + tid] = 1.0f;       // E = I
    __syncthreads();

    // Fused elimination: per step k, rows i>k do
    //   A[i][j] -= c_i * A[k][j]  (j = k+1..i, via colbuf = column k)
    //   E[i][j] -= c_i * E[k][j]  (j = 0..k; E[k][k] = 1)
    for (int k = 0; k < NDIM - 1; ++k) {
        if (tid < NDIM) colbuf[tid] = A[tid * AST + k];
        if (tid == 0) dinvsh = 1.0f / A[k * AST + k];
        __syncthreads();
        if (row > k) {
            float c = colbuf[row] * dinvsh;
            ull nc2 = dup2(-c);
            if (isE) {
                float* Er = E + row * AST;
                const float* Ek = E + k * AST;
                int j = 0;
                #pragma unroll 4
                for (; j + 1 <= k; j += 2) {
                    ull e2 = *reinterpret_cast<ull*>(Er + j);
                    ull k2 = *reinterpret_cast<const ull*>(Ek + j);
                    *reinterpret_cast<ull*>(Er + j) = fma2(nc2, k2, e2);
                }
                if (j == k) Er[j] = fmaf(-c, Ek[j], Er[j]);   // Ek[k] = 1
            } else {
                float* Ar = A + row * AST;
                int j = k + 1;
                if (j & 1) { Ar[j] = fmaf(-c, colbuf[j], Ar[j]); ++j; }
                #pragma unroll 4
                for (; j + 1 <= row; j += 2) {
                    ull a2 = *reinterpret_cast<ull*>(Ar + j);
                    ull c2 = *reinterpret_cast<const ull*>(colbuf + j);
                    *reinterpret_cast<ull*>(Ar + j) = fma2(nc2, c2, a2);
                }
                if (j == row) Ar[j] = fmaf(-c, colbuf[j], Ar[j]);
            }
        }
        __syncthreads();
    }

    // Diagonal D -> rinv, logdet
    if (tid < NDIM) {
        float d = A[tid * AST + tid];
        rinv[tid] = 1.0f / sqrtf(d);
        lbuf[tid] = logf(d);
    }
    __syncthreads();
    if (tid == 0) {
        float s = 0.0f;
        for (int j = 0; j < NDIM; ++j) s += lbuf[j];
        g_logdet[bk] = 0.5f * s;
    }

    // negc[i] = -rinv[i] * sum_{j<=i} E[i][j] * mu[j]   (E[i][i] = 1)
    if (tid < NDIM) {
        const int i = tid;
        const float* Er = E + i * AST;
        float s0 = 0.f, s1 = 0.f, s2 = 0.f, s3 = 0.f;
        int j = 0;
        for (; j + 3 <= i; j += 4) {
            s0 = fmaf(Er[j],     mush[j],     s0);
            s1 = fmaf(Er[j + 1], mush[j + 1], s1);
            s2 = fmaf(Er[j + 2], mush[j + 2], s2);
            s3 = fmaf(Er[j + 3], mush[j + 3], s3);
        }
        for (; j <= i; ++j) s0 = fmaf(Er[j], mush[j], s0);
        g_negc[(size_t)bk * NDIM + i] = -rinv[i] * ((s0 + s1) + (s2 + s3));
    }

    // Store transposed inverse: minvT[j][i] = rinv[i] * E[i][j]  (i >= j)
    float* out = g_minvT + (size_t)bk * NDIM * NDIM;
    for (int idx = tid; idx < NDIM * NDIM; idx += 160) {
        int j = idx / NDIM, c = idx % NDIM;
        float v;
        if (c > j)       v = rinv[c] * E[c * AST + j];
        else if (c == j) v = rinv[c];
        else             v = 0.0f;
        out[idx] = v;
    }
}

// ---------------------------------------------------------------------------
// Kernel B: block = (s-tile, k-group of 3, b). x staged (transposed) ONCE,
// reused across 3 k's. Per k: stage msh + negc, mainloop (row-paired f32x2,
// d-prefetch), epilogue z = Mx - c, quad, ll. (unchanged from R7)
// ---------------------------------------------------------------------------
__global__ __launch_bounds__(320, 3) void ll_kernel(const float* __restrict__ x,
                                                    float* __restrict__ out) {
    extern __shared__ float sm[];
    float* msh = sm;                        // [NDIM][MST]
    float* ds  = sm + NDIM * MST;           // [NDIM][DST]  x transposed [n][s]
    float* red = ds + NDIM * DST;           // [10][DST]    reduction scratch

    const int tid = threadIdx.x;
    const int tx  = tid & 31;
    const int ty  = tid >> 5;               // warp id 0..9
    const int s0  = blockIdx.x * ST;
    const int kg  = blockIdx.y;
    const int b   = blockIdx.z;

    int navail = SEQ - s0; if (navail > ST) navail = ST;
    const float* xb = x + ((size_t)b * SEQ + s0) * NDIM;

    for (int t = tid; t < (NDIM / 4) * ST; t += 320) {
        int n4 = t / ST;
        int s  = t - n4 * ST;
        float4 v = make_float4(0.f, 0.f, 0.f, 0.f);
        if (s < navail)
            v = *reinterpret_cast<const float4*>(xb + (size_t)s * NDIM + 4 * n4);
        ds[(4 * n4 + 0) * DST + s] = v.x;
        ds[(4 * n4 + 1) * DST + s] = v.y;
        ds[(4 * n4 + 2) * DST + s] = v.z;
        ds[(4 * n4 + 3) * DST + s] = v.w;
    }

    const int rlo = 4 * ty;
    const int rhi = 76 - 4 * ty;
    const int jA  = rlo + 4;
    const int jB  = 80 - rlo;

    for (int kk = 0; kk < KPB; ++kk) {
        const int k  = kg * KPB + kk;
        const int bk = b * KST + k;

        __syncthreads();
        const float* mv = g_minvT + (size_t)bk * NDIM * NDIM;
        for (int idx = tid; idx < NDIM * NDIM; idx += 320) {
            int j = idx / NDIM, i2 = idx - j * NDIM;
            msh[j * MST + i2] = __ldg(mv + idx);
        }
        float* ncsh = red + DST;
        if (tid < NDIM) ncsh[tid] = __ldg(g_negc + (size_t)bk * NDIM + tid);
        __syncthreads();

        ull acc[4][4];
        #pragma unroll
        for (int p = 0; p < 4; ++p)
            #pragma unroll
            for (int s = 0; s < 4; ++s) acc[p][s] = 0ULL;

        const float* mlo = msh + rlo;
        const float* mhi = msh + rhi;
        const float* dp  = ds + 4 * tx;
        float4 d4 = *reinterpret_cast<const float4*>(dp);
        dp += DST;

        #pragma unroll 2
        for (int j = 0; j < jA; ++j) {
            ulonglong2 mlp = *reinterpret_cast<const ulonglong2*>(mlo);
            ulonglong2 mhp = *reinterpret_cast<const ulonglong2*>(mhi);
            float4 dn = *reinterpret_cast<const float4*>(dp);
            ull d0 = dup2(d4.x), d1 = dup2(d4.y), d2 = dup2(d4.z), d3 = dup2(d4.w);
            acc[0][0]=fma2(mlp.x,d0,acc[0][0]); acc[0][1]=fma2(mlp.x,d1,acc[0][1]); acc[0][2]=fma2(mlp.x,d2,acc[0][2]); acc[0][3]=fma2(mlp.x,d3,acc[0][3]);
            acc[1][0]=fma2(mlp.y,d0,acc[1][0]); acc[1][1]=fma2(mlp.y,d1,acc[1][1]); acc[1][2]=fma2(mlp.y,d2,acc[1][2]); acc[1][3]=fma2(mlp.y,d3,acc[1][3]);
            acc[2][0]=fma2(mhp.x,d0,acc[2][0]); acc[2][1]=fma2(mhp.x,d1,acc[2][1]); acc[2][2]=fma2(mhp.x,d2,acc[2][2]); acc[2][3]=fma2(mhp.x,d3,acc[2][3]);
            acc[3][0]=fma2(mhp.y,d0,acc[3][0]); acc[3][1]=fma2(mhp.y,d1,acc[3][1]); acc[3][2]=fma2(mhp.y,d2,acc[3][2]); acc[3][3]=fma2(mhp.y,d3,acc[3][3]);
            d4 = dn; mlo += MST; mhi += MST; dp += DST;
        }
        #pragma unroll 4
        for (int j = jA; j < jB; ++j) {
            ulonglong2 mhp = *reinterpret_cast<const ulonglong2*>(mhi);
            float4 dn = *reinterpret_cast<const float4*>(dp);   // last lands in red (safe)
            ull d0 = dup2(d4.x), d1 = dup2(d4.y), d2 = dup2(d4.z), d3 = dup2(d4.w);
            acc[2][0]=fma2(mhp.x,d0,acc[2][0]); acc[2][1]=fma2(mhp.x,d1,acc[2][1]); acc[2][2]=fma2(mhp.x,d2,acc[2][2]); acc[2][3]=fma2(mhp.x,d3,acc[2][3]);
            acc[3][0]=fma2(mhp.y,d0,acc[3][0]); acc[3][1]=fma2(mhp.y,d1,acc[3][1]); acc[3][2]=fma2(mhp.y,d2,acc[3][2]); acc[3][3]=fma2(mhp.y,d3,acc[3][3]);
            d4 = dn; mhi += MST; dp += DST;
        }

        ull ncl0 = *reinterpret_cast<const ull*>(ncsh + rlo);
        ull ncl1 = *reinterpret_cast<const ull*>(ncsh + rlo + 2);
        ull nch0 = *reinterpret_cast<const ull*>(ncsh + rhi);
        ull nch1 = *reinterpret_cast<const ull*>(ncsh + rhi + 2);
        float4 q;
        float* qf = reinterpret_cast<float*>(&q);
        #pragma unroll
        for (int s = 0; s < 4; ++s) {
            ull z0 = add2(acc[0][s], ncl0);
            ull z1 = add2(acc[1][s], ncl1);
            ull z2 = add2(acc[2][s], nch0);
            ull z3 = add2(acc[3][s], nch1);
            ull t = mul2(z0, z0);
            t = fma2(z1, z1, t);
            t = fma2(z2, z2, t);
            t = fma2(z3, z3, t);
            float2 f = asf2(t);
            qf[s] = f.x + f.y;
        }

        __syncthreads();
        *reinterpret_cast<float4*>(red + ty * DST + 4 * tx) = q;
        __syncthreads();

        if (tid < ST && tid < navail) {
            float sum = 0.0f;
            #pragma unroll
            for (int t = 0; t < 10; ++t) sum += red[t * DST + tid];
            float ll = -0.5f * sum - __ldg(g_logdet + bk) - 0.5f * (float)NDIM * LOG_2PI;
            out[((size_t)b * SEQ + s0 + tid) * KST + k] = ll;
        }
    }
}

// ---------------------------------------------------------------------------
extern "C" void kernel_launch(void* const* d_in, const int* in_sizes, int n_in,
                              void* d_out, int out_size) {
    const float* x     = (const float*)d_in[0];
    const float* mu    = (const float*)d_in[1];
    const float* sigma = (const float*)d_in[2];
    float* out = (float*)d_out;

    const int llsmem = (NDIM * MST + NDIM * DST + 10 * DST) * sizeof(float);  // 74400 B
    cudaFuncSetAttribute(ll_kernel, cudaFuncAttributeMaxDynamicSharedMemorySize, llsmem);

    chol_inv_kernel<<<NBK, 160>>>(sigma, mu);

    dim3 grid((SEQ + ST - 1) / ST, KGRP, BATCH);
    ll_kernel<<<grid, 320, llsmem>>>(x, out);
}

// round 9
// speedup vs baseline: 1.1783x; 1.1783x over previous
#include <cuda_runtime.h>
#include <math.h>

constexpr int NDIM  = 80;
constexpr int BATCH = 64;
constexpr int SEQ   = 1000;
constexpr int KST   = 12;
constexpr int NBK   = BATCH * KST;   // 768
constexpr int ST    = 128;           // samples per block (kernel B)
constexpr int KPB   = 3;             // k's per block
constexpr int KGRP  = KST / KPB;     // 4
constexpr int MST   = 84;            // msh row stride
constexpr int DST   = 132;           // ds row stride
constexpr int AST   = 84;            // chol A row stride (16B-aligned rows, conflict-free LDS.128)

constexpr float LOG_2PI = 1.837877066409345339082f;
constexpr float EPS = 1e-5f;

__device__ float g_minvT[(size_t)NBK * NDIM * NDIM];
__device__ float g_logdet[NBK];
__device__ float g_negc[(size_t)NBK * NDIM];   // -Lc^-1*mu per (b,k)

typedef unsigned long long ull;
__device__ __forceinline__ ull fma2(ull a, ull b, ull c) {
    ull d; asm("fma.rn.f32x2 %0,%1,%2,%3;" : "=l"(d) : "l"(a), "l"(b), "l"(c)); return d;
}
__device__ __forceinline__ ull mul2(ull a, ull b) {
    ull d; asm("mul.rn.f32x2 %0,%1,%2;" : "=l"(d) : "l"(a), "l"(b)); return d;
}
__device__ __forceinline__ ull add2(ull a, ull b) {
    ull d; asm("add.rn.f32x2 %0,%1,%2;" : "=l"(d) : "l"(a), "l"(b)); return d;
}
__device__ __forceinline__ ull dup2(float x) {
    ull d; asm("mov.b64 %0,{%1,%1};" : "=l"(d) : "f"(x)); return d;
}
__device__ __forceinline__ float2 asf2(ull v) {
    float2 r; asm("mov.b64 {%0,%1},%2;" : "=f"(r.x), "=f"(r.y) : "l"(v)); return r;
}

// ---------------------------------------------------------------------------
// Kernel A: per (b,k). Elimination with LDS.128-vectorized rank-1 updates,
// scale to Cholesky L, logdet, sync-free triangular inverse into the upper
// triangle (column i private to thread i), negc = -Lc^-1*mu, dense store.
// 96 threads, thread i owns row i.
// ---------------------------------------------------------------------------
__global__ __launch_bounds__(96) void chol_inv_kernel(const float* __restrict__ sigma,
                                                      const float* __restrict__ mu) {
    __shared__ __align__(16) float A[NDIM * AST];      // 26.9 KB
    __shared__ __align__(16) float colbuf[NDIM + 4];
    __shared__ __align__(16) float rinv[NDIM];
    __shared__ float lbuf[NDIM];
    __shared__ float mush[NDIM];
    __shared__ float dinvsh;

    const int bk  = blockIdx.x;
    const int tid = threadIdx.x;
    const int i   = tid;
    const float* Sg = sigma + (size_t)bk * NDIM * NDIM;

    for (int idx = tid; idx < NDIM * NDIM; idx += 96) {
        int r = idx / NDIM, c = idx % NDIM;
        float v = Sg[idx];
        if (r == c) v += EPS;
        A[r * AST + c] = v;
    }
    __syncthreads();

    // Elimination: A[i][j] -= (A[i][k]/A[k][k]) * A[j][k], j = k+1..i
    for (int k = 0; k < NDIM - 1; ++k) {
        if (tid < NDIM) colbuf[tid] = A[tid * AST + k];
        if (tid == 0) dinvsh = 1.0f / A[k * AST + k];
        __syncthreads();
        if (i > k && i < NDIM) {
            float nci = -colbuf[i] * dinvsh;
            ull  nc2 = dup2(nci);
            float* Ai = A + i * AST;
            int j = k + 1;
            // scalar head to 16B alignment
            for (; j <= i && (j & 3); ++j) Ai[j] = fmaf(nci, colbuf[j], Ai[j]);
            // vector body: LDS.128 / 2xFFMA2 / STS.128
            #pragma unroll 2
            for (; j + 3 <= i; j += 4) {
                ulonglong2 a2 = *reinterpret_cast<ulonglong2*>(Ai + j);
                ulonglong2 c2 = *reinterpret_cast<const ulonglong2*>(colbuf + j);
                a2.x = fma2(nc2, c2.x, a2.x);
                a2.y = fma2(nc2, c2.y, a2.y);
                *reinterpret_cast<ulonglong2*>(Ai + j) = a2;
            }
            // scalar tail
            for (; j <= i; ++j) Ai[j] = fmaf(nci, colbuf[j], Ai[j]);
        }
        __syncthreads();
    }

    // Diagonal -> rinv, logdet
    if (tid < NDIM) {
        float d = A[tid * AST + tid];
        rinv[tid] = 1.0f / sqrtf(d);
        lbuf[tid] = logf(d);
    }
    if (tid < NDIM) mush[tid] = mu[(size_t)bk * NDIM + tid];
    __syncthreads();
    if (tid == 0) {
        float s = 0.0f;
        for (int j = 0; j < NDIM; ++j) s += lbuf[j];
        g_logdet[bk] = 0.5f * s;
    }
    // Scale lower part to Cholesky L: L[i][k] = A[i][k] * rinv[k]  (k < i)
    if (i < NDIM) {
        float* Ai = A + i * AST;
        int k = 0;
        #pragma unroll 2
        for (; k + 3 <= i - 1; k += 4) {
            ulonglong2 a2 = *reinterpret_cast<ulonglong2*>(Ai + k);
            ulonglong2 r2 = *reinterpret_cast<const ulonglong2*>(rinv + k);
            a2.x = mul2(a2.x, r2.x);
            a2.y = mul2(a2.y, r2.y);
            *reinterpret_cast<ulonglong2*>(Ai + k) = a2;
        }
        for (; k <= i - 1; ++k) Ai[k] *= rinv[k];
    }
    __syncthreads();

    // Sync-free triangular inverse X = L^-1 into the UPPER triangle
    // (column i written only by thread i; reads own prior writes + stable L).
    if (i > 0 && i < NDIM) {
        for (int jj = i - 1; jj >= 0; --jj) {
            float s0 = rinv[i] * A[i * AST + jj];
            float s1 = 0.f, s2 = 0.f, s3 = 0.f;
            int k = jj + 1;
            for (; k + 3 < i; k += 4) {
                s0 = fmaf(A[k * AST + i],     A[k * AST + jj],     s0);
                s1 = fmaf(A[(k+1) * AST + i], A[(k+1) * AST + jj], s1);
                s2 = fmaf(A[(k+2) * AST + i], A[(k+2) * AST + jj], s2);
                s3 = fmaf(A[(k+3) * AST + i], A[(k+3) * AST + jj], s3);
            }
            for (; k < i; ++k)
                s0 = fmaf(A[k * AST + i], A[k * AST + jj], s0);
            A[jj * AST + i] = -rinv[jj] * ((s0 + s1) + (s2 + s3));
        }
    }
    __syncthreads();

    // negc[i] = -(X[i][i]*mu[i] + sum_{jj<i} X[i][jj]*mu[jj]);  X[i][jj] at A[jj][i]
    if (i < NDIM) {
        float s = rinv[i] * mush[i];
        for (int jj = 0; jj < i; ++jj)
            s = fmaf(A[jj * AST + i], mush[jj], s);
        g_negc[(size_t)bk * NDIM + i] = -s;
    }

    // Store dense transposed inverse: out[j][c] = X[c][j]
    float* out = g_minvT + (size_t)bk * NDIM * NDIM;
    for (int idx = tid; idx < NDIM * NDIM; idx += 96) {
        int j = idx / NDIM, c = idx % NDIM;
        float v;
        if (c > j)       v = A[j * AST + c];
        else if (c == j) v = rinv[c];
        else             v = 0.0f;
        out[idx] = v;
    }
}

// ---------------------------------------------------------------------------
// Kernel B: block = (s-tile, k-group of 3, b). x staged (transposed) ONCE,
// reused across 3 k's. Per k: stage msh + negc, mainloop (row-paired f32x2,
// d-prefetch), epilogue z = Mx - c, quad, ll. (unchanged, measured 162us)
// ---------------------------------------------------------------------------
__global__ __launch_bounds__(320, 3) void ll_kernel(const float* __restrict__ x,
                                                    float* __restrict__ out) {
    extern __shared__ float sm[];
    float* msh = sm;                        // [NDIM][MST]
    float* ds  = sm + NDIM * MST;           // [NDIM][DST]  x transposed [n][s]
    float* red = ds + NDIM * DST;           // [10][DST]    reduction scratch

    const int tid = threadIdx.x;
    const int tx  = tid & 31;
    const int ty  = tid >> 5;               // warp id 0..9
    const int s0  = blockIdx.x * ST;
    const int kg  = blockIdx.y;
    const int b   = blockIdx.z;

    int navail = SEQ - s0; if (navail > ST) navail = ST;
    const float* xb = x + ((size_t)b * SEQ + s0) * NDIM;

    for (int t = tid; t < (NDIM / 4) * ST; t += 320) {
        int n4 = t / ST;
        int s  = t - n4 * ST;
        float4 v = make_float4(0.f, 0.f, 0.f, 0.f);
        if (s < navail)
            v = *reinterpret_cast<const float4*>(xb + (size_t)s * NDIM + 4 * n4);
        ds[(4 * n4 + 0) * DST + s] = v.x;
        ds[(4 * n4 + 1) * DST + s] = v.y;
        ds[(4 * n4 + 2) * DST + s] = v.z;
        ds[(4 * n4 + 3) * DST + s] = v.w;
    }

    const int rlo = 4 * ty;
    const int rhi = 76 - 4 * ty;
    const int jA  = rlo + 4;
    const int jB  = 80 - rlo;

    for (int kk = 0; kk < KPB; ++kk) {
        const int k  = kg * KPB + kk;
        const int bk = b * KST + k;

        __syncthreads();
        const float* mv = g_minvT + (size_t)bk * NDIM * NDIM;
        for (int idx = tid; idx < NDIM * NDIM; idx += 320) {
            int j = idx / NDIM, i2 = idx - j * NDIM;
            msh[j * MST + i2] = __ldg(mv + idx);
        }
        float* ncsh = red + DST;
        if (tid < NDIM) ncsh[tid] = __ldg(g_negc + (size_t)bk * NDIM + tid);
        __syncthreads();

        ull acc[4][4];
        #pragma unroll
        for (int p = 0; p < 4; ++p)
            #pragma unroll
            for (int s = 0; s < 4; ++s) acc[p][s] = 0ULL;

        const float* mlo = msh + rlo;
        const float* mhi = msh + rhi;
        const float* dp  = ds + 4 * tx;
        float4 d4 = *reinterpret_cast<const float4*>(dp);
        dp += DST;

        #pragma unroll 2
        for (int j = 0; j < jA; ++j) {
            ulonglong2 mlp = *reinterpret_cast<const ulonglong2*>(mlo);
            ulonglong2 mhp = *reinterpret_cast<const ulonglong2*>(mhi);
            float4 dn = *reinterpret_cast<const float4*>(dp);
            ull d0 = dup2(d4.x), d1 = dup2(d4.y), d2 = dup2(d4.z), d3 = dup2(d4.w);
            acc[0][0]=fma2(mlp.x,d0,acc[0][0]); acc[0][1]=fma2(mlp.x,d1,acc[0][1]); acc[0][2]=fma2(mlp.x,d2,acc[0][2]); acc[0][3]=fma2(mlp.x,d3,acc[0][3]);
            acc[1][0]=fma2(mlp.y,d0,acc[1][0]); acc[1][1]=fma2(mlp.y,d1,acc[1][1]); acc[1][2]=fma2(mlp.y,d2,acc[1][2]); acc[1][3]=fma2(mlp.y,d3,acc[1][3]);
            acc[2][0]=fma2(mhp.x,d0,acc[2][0]); acc[2][1]=fma2(mhp.x,d1,acc[2][1]); acc[2][2]=fma2(mhp.x,d2,acc[2][2]); acc[2][3]=fma2(mhp.x,d3,acc[2][3]);
            acc[3][0]=fma2(mhp.y,d0,acc[3][0]); acc[3][1]=fma2(mhp.y,d1,acc[3][1]); acc[3][2]=fma2(mhp.y,d2,acc[3][2]); acc[3][3]=fma2(mhp.y,d3,acc[3][3]);
            d4 = dn; mlo += MST; mhi += MST; dp += DST;
        }
        #pragma unroll 4
        for (int j = jA; j < jB; ++j) {
            ulonglong2 mhp = *reinterpret_cast<const ulonglong2*>(mhi);
            float4 dn = *reinterpret_cast<const float4*>(dp);   // last lands in red (safe)
            ull d0 = dup2(d4.x), d1 = dup2(d4.y), d2 = dup2(d4.z), d3 = dup2(d4.w);
            acc[2][0]=fma2(mhp.x,d0,acc[2][0]); acc[2][1]=fma2(mhp.x,d1,acc[2][1]); acc[2][2]=fma2(mhp.x,d2,acc[2][2]); acc[2][3]=fma2(mhp.x,d3,acc[2][3]);
            acc[3][0]=fma2(mhp.y,d0,acc[3][0]); acc[3][1]=fma2(mhp.y,d1,acc[3][1]); acc[3][2]=fma2(mhp.y,d2,acc[3][2]); acc[3][3]=fma2(mhp.y,d3,acc[3][3]);
            d4 = dn; mhi += MST; dp += DST;
        }

        ull ncl0 = *reinterpret_cast<const ull*>(ncsh + rlo);
        ull ncl1 = *reinterpret_cast<const ull*>(ncsh + rlo + 2);
        ull nch0 = *reinterpret_cast<const ull*>(ncsh + rhi);
        ull nch1 = *reinterpret_cast<const ull*>(ncsh + rhi + 2);
        float4 q;
        float* qf = reinterpret_cast<float*>(&q);
        #pragma unroll
        for (int s = 0; s < 4; ++s) {
            ull z0 = add2(acc[0][s], ncl0);
            ull z1 = add2(acc[1][s], ncl1);
            ull z2 = add2(acc[2][s], nch0);
            ull z3 = add2(acc[3][s], nch1);
            ull t = mul2(z0, z0);
            t = fma2(z1, z1, t);
            t = fma2(z2, z2, t);
            t = fma2(z3, z3, t);
            float2 f = asf2(t);
            qf[s] = f.x + f.y;
        }

        __syncthreads();
        *reinterpret_cast<float4*>(red + ty * DST + 4 * tx) = q;
        __syncthreads();

        if (tid < ST && tid < navail) {
            float sum = 0.0f;
            #pragma unroll
            for (int t = 0; t < 10; ++t) sum += red[t * DST + tid];
            float ll = -0.5f * sum - __ldg(g_logdet + bk) - 0.5f * (float)NDIM * LOG_2PI;
            out[((size_t)b * SEQ + s0 + tid) * KST + k] = ll;
        }
    }
}

// ---------------------------------------------------------------------------
extern "C" void kernel_launch(void* const* d_in, const int* in_sizes, int n_in,
                              void* d_out, int out_size) {
    const float* x     = (const float*)d_in[0];
    const float* mu    = (const float*)d_in[1];
    const float* sigma = (const float*)d_in[2];
    float* out = (float*)d_out;

    const int llsmem = (NDIM * MST + NDIM * DST + 10 * DST) * sizeof(float);  // 74400 B
    cudaFuncSetAttribute(ll_kernel, cudaFuncAttributeMaxDynamicSharedMemorySize, llsmem);

    chol_inv_kernel<<<NBK, 96>>>(sigma, mu);

    dim3 grid((SEQ + ST - 1) / ST, KGRP, BATCH);
    ll_kernel<<<grid, 320, llsmem>>>(x, out);
}